// round 12
// baseline (speedup 1.0000x reference)
#include <cuda_runtime.h>
#include <math.h>
#include <stdint.h>

#define D_MODEL 768
#define D_HID   3072
#define NUM_EXPERTS 8
#define NTOK    2048
#define NSLOT   (NTOK * 2)

// ---------------- device scratch (no runtime allocation allowed) ----------------
__device__ float g_hidden[NSLOT * D_HID];   // tf32-pre-rounded gelu(x@W1)
__device__ float g_y[NSLOT * D_MODEL];
__device__ int   g_cnt[NUM_EXPERTS];
__device__ int   g_rows[NUM_EXPERTS * NTOK];
__device__ float g_wt[NSLOT];

// ---------------- reset ----------------------------------------------------------
__global__ void reset_kernel() {
    if (threadIdx.x < NUM_EXPERTS) g_cnt[threadIdx.x] = 0;
}

// ---------------- router (exact fp32; assignment must match reference) -----------
__global__ void router_kernel(const float* __restrict__ x,
                              const float* __restrict__ gw) {
    __shared__ float xs[D_MODEL];
    __shared__ float logits[NUM_EXPERTS];
    const int n = blockIdx.x;
    const float* xr = x + (size_t)n * D_MODEL;
    for (int i = threadIdx.x; i < D_MODEL; i += blockDim.x) xs[i] = xr[i];
    __syncthreads();

    const int w = threadIdx.x >> 5, lane = threadIdx.x & 31;
    if (w < NUM_EXPERTS) {
        float s = 0.f;
        for (int d = lane; d < D_MODEL; d += 32)
            s += xs[d] * gw[d * NUM_EXPERTS + w];
        #pragma unroll
        for (int o = 16; o; o >>= 1) s += __shfl_xor_sync(0xffffffffu, s, o);
        if (lane == 0) logits[w] = s;
    }
    __syncthreads();

    if (threadIdx.x == 0) {
        int i0 = 0; float l0 = logits[0];
        #pragma unroll
        for (int e = 1; e < NUM_EXPERTS; e++)
            if (logits[e] > l0) { l0 = logits[e]; i0 = e; }
        int i1 = -1; float l1 = -INFINITY;
        #pragma unroll
        for (int e = 0; e < NUM_EXPERTS; e++)
            if (e != i0 && logits[e] > l1) { l1 = logits[e]; i1 = e; }
        float e1 = expf(l1 - l0);
        float inv = 1.f / (1.f + e1);

        int p0 = atomicAdd(&g_cnt[i0], 1);
        g_rows[i0 * NTOK + p0] = n * 2 + 0;
        g_wt[n * 2 + 0] = inv;
        int p1 = atomicAdd(&g_cnt[i1], 1);
        g_rows[i1 * NTOK + p1] = n * 2 + 1;
        g_wt[n * 2 + 1] = e1 * inv;
    }
}

// ---------------- tf32 helpers --------------------------------------------------
__device__ __forceinline__ unsigned f2tf32(float f) {
    unsigned u;
    asm("cvt.rna.tf32.f32 %0, %1;" : "=r"(u) : "f"(f));
    return u;
}
__device__ __forceinline__ void mma_tf32(float* c,
                                         unsigned a0, unsigned a1, unsigned a2, unsigned a3,
                                         unsigned b0, unsigned b1) {
    asm volatile(
        "mma.sync.aligned.m16n8k8.row.col.f32.tf32.tf32.f32 "
        "{%0,%1,%2,%3}, {%4,%5,%6,%7}, {%8,%9}, {%0,%1,%2,%3};"
        : "+f"(c[0]), "+f"(c[1]), "+f"(c[2]), "+f"(c[3])
        : "r"(a0), "r"(a1), "r"(a2), "r"(a3), "r"(b0), "r"(b1));
}

// ---------------- grouped tensor-core GEMM: BM=64, BN=128, BK=32 ----------------
// Pair-interleaved smem: element (s, q) stores float2(val[8s+q], val[8s+q+4]) so
// every tf32 fragment operand pair is ONE LDS.64.
//   A slot stride 68 f2 : load bank-pair = (4*qid + grp) mod 16  -> bijective
//   B slot stride 140 f2: load bank-pair = (12*qid + grp + 8j)   -> bijective
// Double-buffered, one __syncthreads per k32 tile (R10-proven schedule).
static constexpr int BM = 64, BN = 128, BK = 32;
static constexpr int ASTR2 = 68;                 // float2 stride per A slot
static constexpr int BSTR2 = 140;                // float2 stride per B slot
static constexpr int SZ_A2 = 16 * ASTR2;         // f2 per A buffer (1088)
static constexpr int SZ_B2 = 16 * BSTR2;         // f2 per B buffer (2240)
static constexpr int OFF_A    = 0;                        // 2 * 8704 B
static constexpr int OFF_B    = 2 * SZ_A2 * 8;            // 17408
static constexpr int OFF_SLOT = OFF_B + 2 * SZ_B2 * 8;    // 53248
static constexpr int SMEM_TOTAL = OFF_SLOT + BM * 4;      // 53504

template<bool GELU, bool HALVE_ROW, bool PREROUNDED>
__device__ __forceinline__ void gemm_tc(
    const float* __restrict__ A, int lda,
    const float* __restrict__ B, int ldb, int Kdim,
    const float* __restrict__ bias,
    float* __restrict__ C, int ldc)
{
    const int e = blockIdx.z;
    const int cnt = g_cnt[e];
    const int m0 = blockIdx.y * BM;
    if (m0 >= cnt) return;
    const int n0 = blockIdx.x * BN;
    const int* rows = g_rows + e * NTOK;
    const float* Be = B + (size_t)e * Kdim * ldb;

    extern __shared__ char sm[];
    uint2* AsAll = (uint2*)(sm + OFF_A);
    uint2* BsAll = (uint2*)(sm + OFF_B);
    int* slotSm = (int*)(sm + OFF_SLOT);

    const int tid  = threadIdx.x;
    const int warp = tid >> 5;
    const int lane = tid & 31;
    const int grp  = lane >> 2;
    const int qid  = lane & 3;

    const int warp_m = warp & 1;
    const int warp_n = warp >> 1;
    const int cbase  = warp_n * 32;

    if (tid < BM) {
        int gr = m0 + tid;
        slotSm[tid] = (gr < cnt) ? rows[gr] : -1;
    }
    __syncthreads();

    // ---- A staging: thread -> (row = tid&63, s = tid>>6); reads row k[8s..8s+7]
    const int arow = tid & 63;
    const int as   = tid >> 6;
    const int asl  = slotSm[arow];
    const bool av  = asl >= 0;
    const float* ap = A + (av ? (size_t)(HALVE_ROW ? (asl >> 1) : asl) * lda : 0) + as * 8;

    // ---- B staging: 2 chunks; chunk -> slot = chunk>>5 (s=slot>>2,q=slot&3), n4
    const int ch0 = tid, ch1 = tid + 256;
    const int bslot0 = ch0 >> 5, bn0_ = (ch0 & 31) * 4;
    const int bslot1 = ch1 >> 5, bn1_ = (ch1 & 31) * 4;
    const float* bp0 = Be + (size_t)((bslot0 >> 2) * 8 + (bslot0 & 3)) * ldb + n0 + bn0_;
    const float* bp1 = Be + (size_t)((bslot1 >> 2) * 8 + (bslot1 & 3)) * ldb + n0 + bn1_;

    float4 av0, av1, bu0[2], bu1[2];
    const int T = Kdim / BK;

    auto pf = [&](int k0) {
        av0 = av ? *(const float4*)(ap + k0)     : make_float4(0.f, 0.f, 0.f, 0.f);
        av1 = av ? *(const float4*)(ap + k0 + 4) : make_float4(0.f, 0.f, 0.f, 0.f);
        bu0[0] = *(const float4*)(bp0 + (size_t)k0 * ldb);
        bu0[1] = *(const float4*)(bp0 + (size_t)(k0 + 4) * ldb);
        bu1[0] = *(const float4*)(bp1 + (size_t)k0 * ldb);
        bu1[1] = *(const float4*)(bp1 + (size_t)(k0 + 4) * ldb);
    };
    auto cvt_ = [&](float f) -> unsigned {
        return PREROUNDED ? __float_as_uint(f) : f2tf32(f);
    };
    auto sts = [&](int buf) {
        uint2* Asb = AsAll + buf * SZ_A2;
        uint2* Bsb = BsAll + buf * SZ_B2;
        // A: 4 conflict-free STS.64 (bank-pair = slot*4 + row mod 16, rows distinct)
        const float* v0 = &av0.x;
        const float* v1 = &av1.x;
        #pragma unroll
        for (int q = 0; q < 4; q++)
            Asb[(as * 4 + q) * ASTR2 + arow] = make_uint2(cvt_(v0[q]), cvt_(v1[q]));
        // B: interleave rows (k, k+4) -> 2x STS.128 per chunk
        {
            uint4* d = (uint4*)&Bsb[bslot0 * BSTR2 + bn0_];
            d[0] = make_uint4(f2tf32(bu0[0].x), f2tf32(bu0[1].x),
                              f2tf32(bu0[0].y), f2tf32(bu0[1].y));
            d[1] = make_uint4(f2tf32(bu0[0].z), f2tf32(bu0[1].z),
                              f2tf32(bu0[0].w), f2tf32(bu0[1].w));
        }
        {
            uint4* d = (uint4*)&Bsb[bslot1 * BSTR2 + bn1_];
            d[0] = make_uint4(f2tf32(bu1[0].x), f2tf32(bu1[1].x),
                              f2tf32(bu1[0].y), f2tf32(bu1[1].y));
            d[1] = make_uint4(f2tf32(bu1[0].z), f2tf32(bu1[1].z),
                              f2tf32(bu1[0].w), f2tf32(bu1[1].w));
        }
    };

    float acc[2][4][4];
    #pragma unroll
    for (int i = 0; i < 2; i++)
        #pragma unroll
        for (int j = 0; j < 4; j++)
            #pragma unroll
            for (int q = 0; q < 4; q++) acc[i][j][q] = 0.f;

    pf(0);
    sts(0);
    pf(BK);

    for (int t = 0; t < T; t++) {
        __syncthreads();
        if (t + 1 < T) {
            sts((t + 1) & 1);
            if (t + 2 < T) pf((t + 2) * BK);
        }
        const uint2* Asb = AsAll + (t & 1) * SZ_A2;
        const uint2* Bsb = BsAll + (t & 1) * SZ_B2;
        #pragma unroll
        for (int s = 0; s < 4; s++) {
            // A: (a0,a2) and (a1,a3) as LDS.64
            uint2 a02[2], a13[2];
            #pragma unroll
            for (int i = 0; i < 2; i++) {
                int mr = warp_m * 32 + i * 16 + grp;
                a02[i] = Asb[(s * 4 + qid) * ASTR2 + mr];
                a13[i] = Asb[(s * 4 + qid) * ASTR2 + mr + 8];
            }
            uint2 b01[4];
            #pragma unroll
            for (int j = 0; j < 4; j++)
                b01[j] = Bsb[(s * 4 + qid) * BSTR2 + cbase + j * 8 + grp];
            #pragma unroll
            for (int j = 0; j < 4; j++)
                #pragma unroll
                for (int i = 0; i < 2; i++)
                    mma_tf32(acc[i][j], a02[i].x, a13[i].x, a02[i].y, a13[i].y,
                             b01[j].x, b01[j].y);
        }
    }

    // epilogue: bias (+ GELU), scatter rows via slot ids
    const float* bpb = bias + (size_t)e * ldc;
    float2 bv[4];
    #pragma unroll
    for (int j = 0; j < 4; j++) {
        int c = n0 + cbase + j * 8 + 2 * qid;
        bv[j] = *(const float2*)(bpb + c);
    }
    #pragma unroll
    for (int i = 0; i < 2; i++) {
        int lbase = warp_m * 32 + i * 16 + grp;
        #pragma unroll
        for (int h = 0; h < 2; h++) {
            int lr = lbase + h * 8;
            int slot = slotSm[lr];
            if (slot >= 0) {
                float* crow = C + (size_t)slot * ldc;
                #pragma unroll
                for (int j = 0; j < 4; j++) {
                    int c = n0 + cbase + j * 8 + 2 * qid;
                    float v0 = acc[i][j][2 * h + 0] + bv[j].x;
                    float v1 = acc[i][j][2 * h + 1] + bv[j].y;
                    if (GELU) {
                        v0 = 0.5f * v0 * (1.f + erff(v0 * 0.70710678118654752f));
                        v1 = 0.5f * v1 * (1.f + erff(v1 * 0.70710678118654752f));
                        // store tf32-pre-rounded so GEMM2 staging skips cvt
                        v0 = __uint_as_float(f2tf32(v0));
                        v1 = __uint_as_float(f2tf32(v1));
                    }
                    *(float2*)(crow + c) = make_float2(v0, v1);
                }
            }
        }
    }
}

__global__ void __launch_bounds__(256, 2)
gemm1_kernel(const float* __restrict__ x, const float* __restrict__ w1,
             const float* __restrict__ b1) {
    gemm_tc<true, true, false>(x, D_MODEL, w1, D_HID, D_MODEL, b1, g_hidden, D_HID);
}

__global__ void __launch_bounds__(256, 2)
gemm2_kernel(const float* __restrict__ w2, const float* __restrict__ b2) {
    gemm_tc<false, false, true>(g_hidden, D_HID, w2, D_MODEL, D_HID, b2, g_y, D_MODEL);
}

// ---------------- weighted combine ----------------------------------------------
__global__ void combine_kernel(float* __restrict__ out) {
    int idx = blockIdx.x * blockDim.x + threadIdx.x;
    int n  = idx / (D_MODEL / 4);
    int d4 = (idx % (D_MODEL / 4)) * 4;
    float w0 = g_wt[2 * n], w1 = g_wt[2 * n + 1];
    float4 y0 = *(const float4*)&g_y[(size_t)(2 * n + 0) * D_MODEL + d4];
    float4 y1 = *(const float4*)&g_y[(size_t)(2 * n + 1) * D_MODEL + d4];
    float4 o;
    o.x = w0 * y0.x + w1 * y1.x;
    o.y = w0 * y0.y + w1 * y1.y;
    o.z = w0 * y0.z + w1 * y1.z;
    o.w = w0 * y0.w + w1 * y1.w;
    *(float4*)&out[(size_t)n * D_MODEL + d4] = o;
}

// ---------------- launcher -------------------------------------------------------
extern "C" void kernel_launch(void* const* d_in, const int* in_sizes, int n_in,
                              void* d_out, int out_size) {
    const float* x      = (const float*)d_in[0];
    const float* gate_w = (const float*)d_in[1];
    const float* w1     = (const float*)d_in[2];
    const float* b1     = (const float*)d_in[3];
    const float* w2     = (const float*)d_in[4];
    const float* b2     = (const float*)d_in[5];
    float* out = (float*)d_out;

    cudaFuncSetAttribute(gemm1_kernel, cudaFuncAttributeMaxDynamicSharedMemorySize, SMEM_TOTAL);
    cudaFuncSetAttribute(gemm2_kernel, cudaFuncAttributeMaxDynamicSharedMemorySize, SMEM_TOTAL);

    reset_kernel<<<1, 32>>>();
    router_kernel<<<NTOK, 256>>>(x, gate_w);
    gemm1_kernel<<<dim3(D_HID / BN, NTOK / BM, NUM_EXPERTS), 256, SMEM_TOTAL>>>(x, w1, b1);
    gemm2_kernel<<<dim3(D_MODEL / BN, NTOK / BM, NUM_EXPERTS), 256, SMEM_TOTAL>>>(w2, b2);
    combine_kernel<<<(NTOK * (D_MODEL / 4)) / 256, 256>>>(out);
}

// round 13
// speedup vs baseline: 1.3006x; 1.3006x over previous
#include <cuda_runtime.h>
#include <math.h>
#include <stdint.h>

#define D_MODEL 768
#define D_HID   3072
#define NUM_EXPERTS 8
#define NTOK    2048
#define NSLOT   (NTOK * 2)

// ---------------- device scratch (no runtime allocation allowed) ----------------
__device__ float g_hidden[NSLOT * D_HID];     // tf32-pre-rounded gelu(x@W1)
__device__ float g_y[NSLOT * D_MODEL];
__device__ int   g_cnt[NUM_EXPERTS];
__device__ int   g_rows[NUM_EXPERTS * NTOK];
__device__ float g_wt[NSLOT];
__device__ float g_w1r[NUM_EXPERTS * D_MODEL * D_HID];   // tf32-rounded W1
__device__ float g_w2r[NUM_EXPERTS * D_HID * D_MODEL];   // tf32-rounded W2
__device__ float g_xr[NTOK * D_MODEL];                   // tf32-rounded x

// ---------------- tf32 helpers --------------------------------------------------
__device__ __forceinline__ unsigned f2tf32(float f) {
    unsigned u;
    asm("cvt.rna.tf32.f32 %0, %1;" : "=r"(u) : "f"(f));
    return u;
}
__device__ __forceinline__ void mma_tf32(float* c,
                                         unsigned a0, unsigned a1, unsigned a2, unsigned a3,
                                         unsigned b0, unsigned b1) {
    asm volatile(
        "mma.sync.aligned.m16n8k8.row.col.f32.tf32.tf32.f32 "
        "{%0,%1,%2,%3}, {%4,%5,%6,%7}, {%8,%9}, {%0,%1,%2,%3};"
        : "+f"(c[0]), "+f"(c[1]), "+f"(c[2]), "+f"(c[3])
        : "r"(a0), "r"(a1), "r"(a2), "r"(a3), "r"(b0), "r"(b1));
}
__device__ __forceinline__ void cpa16(uint32_t dst, const void* src, int sz) {
    asm volatile("cp.async.ca.shared.global [%0], [%1], 16, %2;"
                 :: "r"(dst), "l"(src), "r"(sz) : "memory");
}

// ---------------- reset ----------------------------------------------------------
__global__ void reset_kernel() {
    if (threadIdx.x < NUM_EXPERTS) g_cnt[threadIdx.x] = 0;
}

// ---------------- preround: rna-round arrays to tf32 once per launch -------------
__global__ void preround_kernel(const float* __restrict__ in, int which, int n4) {
    float4* out = which == 0 ? (float4*)g_w1r
                : which == 1 ? (float4*)g_w2r
                             : (float4*)g_xr;
    int i = blockIdx.x * blockDim.x + threadIdx.x;
    if (i < n4) {
        float4 v = ((const float4*)in)[i];
        float4 o;
        o.x = __uint_as_float(f2tf32(v.x));
        o.y = __uint_as_float(f2tf32(v.y));
        o.z = __uint_as_float(f2tf32(v.z));
        o.w = __uint_as_float(f2tf32(v.w));
        out[i] = o;
    }
}

// ---------------- router (exact fp32; assignment must match reference) -----------
__global__ void router_kernel(const float* __restrict__ x,
                              const float* __restrict__ gw) {
    __shared__ float xs[D_MODEL];
    __shared__ float logits[NUM_EXPERTS];
    const int n = blockIdx.x;
    const float* xr = x + (size_t)n * D_MODEL;
    for (int i = threadIdx.x; i < D_MODEL; i += blockDim.x) xs[i] = xr[i];
    __syncthreads();

    const int w = threadIdx.x >> 5, lane = threadIdx.x & 31;
    if (w < NUM_EXPERTS) {
        float s = 0.f;
        for (int d = lane; d < D_MODEL; d += 32)
            s += xs[d] * gw[d * NUM_EXPERTS + w];
        #pragma unroll
        for (int o = 16; o; o >>= 1) s += __shfl_xor_sync(0xffffffffu, s, o);
        if (lane == 0) logits[w] = s;
    }
    __syncthreads();

    if (threadIdx.x == 0) {
        int i0 = 0; float l0 = logits[0];
        #pragma unroll
        for (int e = 1; e < NUM_EXPERTS; e++)
            if (logits[e] > l0) { l0 = logits[e]; i0 = e; }
        int i1 = -1; float l1 = -INFINITY;
        #pragma unroll
        for (int e = 0; e < NUM_EXPERTS; e++)
            if (e != i0 && logits[e] > l1) { l1 = logits[e]; i1 = e; }
        float e1 = expf(l1 - l0);
        float inv = 1.f / (1.f + e1);

        int p0 = atomicAdd(&g_cnt[i0], 1);
        g_rows[i0 * NTOK + p0] = n * 2 + 0;
        g_wt[n * 2 + 0] = inv;
        int p1 = atomicAdd(&g_cnt[i1], 1);
        g_rows[i1 * NTOK + p1] = n * 2 + 1;
        g_wt[n * 2 + 1] = e1 * inv;
    }
}

// ---------------- grouped tensor-core GEMM: BM=64, BN=128, BK=32 ----------------
// R10's proven tile/layout (A pad stride 36, B stride 136, 2x4 warp grid,
// 32x32 warp tile). Staging is pure cp.async of pre-rounded data into a
// 3-stage ring; one __syncthreads per tile.
static constexpr int BM = 64, BN = 128, BK = 32;
static constexpr int ASTR = BK + 4;   // 36
static constexpr int BSTR = BN + 8;   // 136
static constexpr int SZ_A = BM * ASTR;                 // 2304 floats (9216 B)
static constexpr int SZ_B = BK * BSTR;                 // 4352 floats (17408 B)
static constexpr int STAGES = 3;
static constexpr int A_BYTES = SZ_A * 4;               // 9216
static constexpr int B_BYTES = SZ_B * 4;               // 17408
static constexpr int OFF_B    = STAGES * A_BYTES;      // 27648
static constexpr int OFF_SLOT = OFF_B + STAGES * B_BYTES;  // 79872
static constexpr int SMEM_TOTAL = OFF_SLOT + BM * 4;       // 80128

template<bool GELU, bool HALVE_ROW>
__device__ __forceinline__ void gemm_tc(
    const float* __restrict__ A, int lda,
    const float* __restrict__ B, int ldb, int Kdim,
    const float* __restrict__ bias,
    float* __restrict__ C, int ldc)
{
    const int e = blockIdx.z;
    const int cnt = g_cnt[e];
    const int m0 = blockIdx.y * BM;
    if (m0 >= cnt) return;
    const int n0 = blockIdx.x * BN;
    const int* rows = g_rows + e * NTOK;
    const float* Be = B + (size_t)e * Kdim * ldb;

    extern __shared__ char sm[];
    int* slotSm = (int*)(sm + OFF_SLOT);
    const uint32_t smBase = (uint32_t)__cvta_generic_to_shared(sm);

    const int tid  = threadIdx.x;
    const int warp = tid >> 5;
    const int lane = tid & 31;
    const int grp  = lane >> 2;
    const int qid  = lane & 3;

    const int warp_m = warp & 1;
    const int warp_n = warp >> 1;
    const int cbase  = warp_n * 32;

    if (tid < BM) {
        int gr = m0 + tid;
        slotSm[tid] = (gr < cnt) ? rows[gr] : -1;
    }
    __syncthreads();

    // ---- A staging: thread -> rows ar0, ar0+32; k-chunk akq*4 (16B)
    const int ar0 = tid >> 3, akq = tid & 7;
    const int sl0 = slotSm[ar0], sl1 = slotSm[ar0 + 32];
    const int szA0 = sl0 >= 0 ? 16 : 0;
    const int szA1 = sl1 >= 0 ? 16 : 0;
    const float* ap0 = A + (sl0 >= 0 ? (size_t)(HALVE_ROW ? (sl0 >> 1) : sl0) * lda : 0) + akq * 4;
    const float* ap1 = A + (sl1 >= 0 ? (size_t)(HALVE_ROW ? (sl1 >> 1) : sl1) * lda : 0) + akq * 4;
    const uint32_t aDst0 = smBase + (uint32_t)(ar0 * ASTR + akq * 4) * 4;
    const uint32_t aDst1 = aDst0 + (uint32_t)(32 * ASTR) * 4;

    // ---- B staging: 4 chunks, rows brow + it*8, cols bc..bc+3 (16B)
    const int brow = tid >> 5;
    const int bc   = lane * 4;
    const float* bp = Be + (size_t)brow * ldb + n0 + bc;
    const uint32_t bDst = smBase + OFF_B + (uint32_t)(brow * BSTR + bc) * 4;

    auto issue = [&](int k0, int s) {
        uint32_t aoff = (uint32_t)s * A_BYTES;
        cpa16(aDst0 + aoff, ap0 + k0, szA0);
        cpa16(aDst1 + aoff, ap1 + k0, szA1);
        uint32_t boff = (uint32_t)s * B_BYTES;
        #pragma unroll
        for (int it = 0; it < 4; it++)
            cpa16(bDst + boff + (uint32_t)(it * 8 * BSTR) * 4,
                  bp + (size_t)(k0 + it * 8) * ldb, 16);
        asm volatile("cp.async.commit_group;" ::: "memory");
    };

    float acc[2][4][4];
    #pragma unroll
    for (int i = 0; i < 2; i++)
        #pragma unroll
        for (int j = 0; j < 4; j++)
            #pragma unroll
            for (int q = 0; q < 4; q++) acc[i][j][q] = 0.f;

    const int T = Kdim / BK;

    issue(0, 0);
    if (T > 1) issue(BK, 1);

    for (int t = 0; t < T; t++) {
        if (t + 1 < T) asm volatile("cp.async.wait_group 1;" ::: "memory");
        else           asm volatile("cp.async.wait_group 0;" ::: "memory");
        __syncthreads();
        if (t + 2 < T) issue((t + 2) * BK, (t + 2) % STAGES);

        const int cs = t % STAGES;
        const unsigned* Asb = (const unsigned*)sm + cs * SZ_A;
        const unsigned* Bsb = (const unsigned*)(sm + OFF_B) + cs * SZ_B;
        #pragma unroll
        for (int ks = 0; ks < 4; ks++) {
            const int k8 = ks * 8;
            unsigned a[2][4];
            #pragma unroll
            for (int i = 0; i < 2; i++) {
                int mr = warp_m * 32 + i * 16 + grp;
                a[i][0] = Asb[mr * ASTR + k8 + qid];
                a[i][1] = Asb[(mr + 8) * ASTR + k8 + qid];
                a[i][2] = Asb[mr * ASTR + k8 + qid + 4];
                a[i][3] = Asb[(mr + 8) * ASTR + k8 + qid + 4];
            }
            unsigned b[4][2];
            #pragma unroll
            for (int j = 0; j < 4; j++) {
                int nc = cbase + j * 8 + grp;
                b[j][0] = Bsb[(k8 + qid) * BSTR + nc];
                b[j][1] = Bsb[(k8 + qid + 4) * BSTR + nc];
            }
            #pragma unroll
            for (int j = 0; j < 4; j++)
                #pragma unroll
                for (int i = 0; i < 2; i++)
                    mma_tf32(acc[i][j], a[i][0], a[i][1], a[i][2], a[i][3],
                             b[j][0], b[j][1]);
        }
        __syncthreads();    // all warps done with slot cs before it is refilled
    }

    // epilogue: bias (+ GELU), scatter rows via slot ids
    const float* bpb = bias + (size_t)e * ldc;
    float2 bv[4];
    #pragma unroll
    for (int j = 0; j < 4; j++) {
        int c = n0 + cbase + j * 8 + 2 * qid;
        bv[j] = *(const float2*)(bpb + c);
    }
    #pragma unroll
    for (int i = 0; i < 2; i++) {
        int lbase = warp_m * 32 + i * 16 + grp;
        #pragma unroll
        for (int h = 0; h < 2; h++) {
            int lr = lbase + h * 8;
            int slot = slotSm[lr];
            if (slot >= 0) {
                float* crow = C + (size_t)slot * ldc;
                #pragma unroll
                for (int j = 0; j < 4; j++) {
                    int c = n0 + cbase + j * 8 + 2 * qid;
                    float v0 = acc[i][j][2 * h + 0] + bv[j].x;
                    float v1 = acc[i][j][2 * h + 1] + bv[j].y;
                    if (GELU) {
                        v0 = 0.5f * v0 * (1.f + erff(v0 * 0.70710678118654752f));
                        v1 = 0.5f * v1 * (1.f + erff(v1 * 0.70710678118654752f));
                        // pre-round so GEMM2 consumes rna-rounded bits w/o cvt
                        v0 = __uint_as_float(f2tf32(v0));
                        v1 = __uint_as_float(f2tf32(v1));
                    }
                    *(float2*)(crow + c) = make_float2(v0, v1);
                }
            }
        }
    }
}

__global__ void __launch_bounds__(256, 2)
gemm1_kernel(const float* __restrict__ b1) {
    gemm_tc<true, true>(g_xr, D_MODEL, g_w1r, D_HID, D_MODEL, b1, g_hidden, D_HID);
}

__global__ void __launch_bounds__(256, 2)
gemm2_kernel(const float* __restrict__ b2) {
    gemm_tc<false, false>(g_hidden, D_HID, g_w2r, D_MODEL, D_HID, b2, g_y, D_MODEL);
}

// ---------------- weighted combine ----------------------------------------------
__global__ void combine_kernel(float* __restrict__ out) {
    int idx = blockIdx.x * blockDim.x + threadIdx.x;
    int n  = idx / (D_MODEL / 4);
    int d4 = (idx % (D_MODEL / 4)) * 4;
    float w0 = g_wt[2 * n], w1 = g_wt[2 * n + 1];
    float4 y0 = *(const float4*)&g_y[(size_t)(2 * n + 0) * D_MODEL + d4];
    float4 y1 = *(const float4*)&g_y[(size_t)(2 * n + 1) * D_MODEL + d4];
    float4 o;
    o.x = w0 * y0.x + w1 * y1.x;
    o.y = w0 * y0.y + w1 * y1.y;
    o.z = w0 * y0.z + w1 * y1.z;
    o.w = w0 * y0.w + w1 * y1.w;
    *(float4*)&out[(size_t)n * D_MODEL + d4] = o;
}

// ---------------- launcher -------------------------------------------------------
extern "C" void kernel_launch(void* const* d_in, const int* in_sizes, int n_in,
                              void* d_out, int out_size) {
    const float* x      = (const float*)d_in[0];
    const float* gate_w = (const float*)d_in[1];
    const float* w1     = (const float*)d_in[2];
    const float* b1     = (const float*)d_in[3];
    const float* w2     = (const float*)d_in[4];
    const float* b2     = (const float*)d_in[5];
    float* out = (float*)d_out;

    cudaFuncSetAttribute(gemm1_kernel, cudaFuncAttributeMaxDynamicSharedMemorySize, SMEM_TOTAL);
    cudaFuncSetAttribute(gemm2_kernel, cudaFuncAttributeMaxDynamicSharedMemorySize, SMEM_TOTAL);

    const int n4_w1 = NUM_EXPERTS * D_MODEL * D_HID / 4;   // 4718592
    const int n4_w2 = NUM_EXPERTS * D_HID * D_MODEL / 4;   // 2359296
    const int n4_x  = NTOK * D_MODEL / 4;                  // 393216

    reset_kernel<<<1, 32>>>();
    router_kernel<<<NTOK, 256>>>(x, gate_w);
    preround_kernel<<<(n4_w1 + 255) / 256, 256>>>(w1, 0, n4_w1);
    preround_kernel<<<(n4_w2 + 255) / 256, 256>>>(w2, 1, n4_w2);
    preround_kernel<<<(n4_x  + 255) / 256, 256>>>(x,  2, n4_x);
    gemm1_kernel<<<dim3(D_HID / BN, NTOK / BM, NUM_EXPERTS), 256, SMEM_TOTAL>>>(b1);
    gemm2_kernel<<<dim3(D_MODEL / BN, NTOK / BM, NUM_EXPERTS), 256, SMEM_TOTAL>>>(b2);
    combine_kernel<<<(NTOK * (D_MODEL / 4)) / 256, 256>>>(out);
}

// round 15
// speedup vs baseline: 1.7696x; 1.3606x over previous
#include <cuda_runtime.h>
#include <cuda_fp16.h>
#include <math.h>
#include <stdint.h>

#define D_MODEL 768
#define D_HID   3072
#define NUM_EXPERTS 8
#define NTOK    2048
#define NSLOT   (NTOK * 2)

// ---------------- device scratch (no runtime allocation allowed) ----------------
__device__ __half   g_hidden_h[NSLOT * D_HID];              // fp16 gelu(x@W1)
__device__ float    g_y[NSLOT * D_MODEL];
__device__ int      g_cnt[NUM_EXPERTS];
__device__ int      g_rows[NUM_EXPERTS * NTOK];
__device__ float    g_wt[NSLOT];
__device__ __half   g_xh[NTOK * D_MODEL];                   // fp16 x
__device__ uint32_t g_w1h[NUM_EXPERTS * (D_MODEL / 2) * D_HID];   // k-pair packed
__device__ uint32_t g_w2h[NUM_EXPERTS * (D_HID / 2) * D_MODEL];   // k-pair packed

// ---------------- helpers --------------------------------------------------------
__device__ __forceinline__ void mma_f16(float* c,
                                        uint32_t a0, uint32_t a1, uint32_t a2, uint32_t a3,
                                        uint32_t b0, uint32_t b1) {
    asm volatile(
        "mma.sync.aligned.m16n8k16.row.col.f32.f16.f16.f32 "
        "{%0,%1,%2,%3}, {%4,%5,%6,%7}, {%8,%9}, {%0,%1,%2,%3};"
        : "+f"(c[0]), "+f"(c[1]), "+f"(c[2]), "+f"(c[3])
        : "r"(a0), "r"(a1), "r"(a2), "r"(a3), "r"(b0), "r"(b1));
}
__device__ __forceinline__ void cpa16(uint32_t dst, const void* src, int sz) {
    asm volatile("cp.async.ca.shared.global [%0], [%1], 16, %2;"
                 :: "r"(dst), "l"(src), "r"(sz) : "memory");
}
__device__ __forceinline__ uint32_t pkh(__half a, __half b) {
    return (uint32_t)__half_as_ushort(a) | ((uint32_t)__half_as_ushort(b) << 16);
}

// ---------------- reset ----------------------------------------------------------
__global__ void reset_kernel() {
    if (threadIdx.x < NUM_EXPERTS) g_cnt[threadIdx.x] = 0;
}

// ---------------- preround: x -> half --------------------------------------------
__global__ void pre_x_kernel(const float* __restrict__ in) {
    int i = blockIdx.x * blockDim.x + threadIdx.x;      // over NTOK*D_MODEL/4
    const float4 v = ((const float4*)in)[i];
    __half2 lo = __floats2half2_rn(v.x, v.y);
    __half2 hi = __floats2half2_rn(v.z, v.w);
    ((uint2*)g_xh)[i] = make_uint2(*(uint32_t*)&lo, *(uint32_t*)&hi);
}

// ---------------- preround: W -> half, k-pair packed -----------------------------
// Destination selected INSIDE device code (device-global symbols must not be
// passed as kernel args from host). out[e][k2][n] = pack(W[e][2k2][n], W[e][2k2+1][n]).
__global__ void pre_w_kernel(const float* __restrict__ in, int which,
                             int K, int N, int total) {
    uint32_t* out = which == 0 ? g_w1h : g_w2h;
    int i = blockIdx.x * blockDim.x + threadIdx.x;
    if (i >= total) return;
    int n = i % N, r = i / N;
    int K2 = K >> 1;
    int e = r / K2, k2 = r % K2;
    const float* p = in + ((size_t)e * K + 2 * k2) * N + n;
    out[i] = pkh(__float2half_rn(p[0]), __float2half_rn(p[N]));
}

// ---------------- router (exact fp32; assignment must match reference) -----------
__global__ void router_kernel(const float* __restrict__ x,
                              const float* __restrict__ gw) {
    __shared__ float xs[D_MODEL];
    __shared__ float logits[NUM_EXPERTS];
    const int n = blockIdx.x;
    const float* xr = x + (size_t)n * D_MODEL;
    for (int i = threadIdx.x; i < D_MODEL; i += blockDim.x) xs[i] = xr[i];
    __syncthreads();

    const int w = threadIdx.x >> 5, lane = threadIdx.x & 31;
    if (w < NUM_EXPERTS) {
        float s = 0.f;
        for (int d = lane; d < D_MODEL; d += 32)
            s += xs[d] * gw[d * NUM_EXPERTS + w];
        #pragma unroll
        for (int o = 16; o; o >>= 1) s += __shfl_xor_sync(0xffffffffu, s, o);
        if (lane == 0) logits[w] = s;
    }
    __syncthreads();

    if (threadIdx.x == 0) {
        int i0 = 0; float l0 = logits[0];
        #pragma unroll
        for (int e = 1; e < NUM_EXPERTS; e++)
            if (logits[e] > l0) { l0 = logits[e]; i0 = e; }
        int i1 = -1; float l1 = -INFINITY;
        #pragma unroll
        for (int e = 0; e < NUM_EXPERTS; e++)
            if (e != i0 && logits[e] > l1) { l1 = logits[e]; i1 = e; }
        float e1 = expf(l1 - l0);
        float inv = 1.f / (1.f + e1);

        int p0 = atomicAdd(&g_cnt[i0], 1);
        g_rows[i0 * NTOK + p0] = n * 2 + 0;
        g_wt[n * 2 + 0] = inv;
        int p1 = atomicAdd(&g_cnt[i1], 1);
        g_rows[i1 * NTOK + p1] = n * 2 + 1;
        g_wt[n * 2 + 1] = e1 * inv;
    }
}

// ---------------- grouped fp16 tensor-core GEMM: BM=64, BN=128, BK=32 ------------
// 8 warps in 2(m)x4(n); warp tile 32x32 = 2 m-frags x 4 n-frags of m16n8k16.
// A smem: [64 rows][32 halves], stride 40 halves. B smem: [16 k2][128 n] word
// pairs, stride 136 words (R10-proven conflict-free pattern).
// 3-stage cp.async ring, ONE __syncthreads per tile (issue t+2 after barrier:
// slot (t+2)%3 was last read in iter t-1, certified done by the barrier).
static constexpr int BM = 64, BN = 128, BK = 32;
static constexpr int ASTRH = 40;                       // halves per A row
static constexpr int A_BYTES = BM * ASTRH * 2;         // 5120
static constexpr int BSTRW = 136;                      // words per B k2-row
static constexpr int B_BYTES = 16 * BSTRW * 4;         // 8704
static constexpr int STAGES = 3;
static constexpr int OFF_B    = STAGES * A_BYTES;      // 15360
static constexpr int OFF_SLOT = OFF_B + STAGES * B_BYTES;  // 41472
static constexpr int SMEM_TOTAL = OFF_SLOT + BM * 4;       // 41728

template<bool G1>
__global__ void __launch_bounds__(256, 2)
moe_gemm(const float* __restrict__ bias) {
    constexpr int KD  = G1 ? D_MODEL : D_HID;          // reduction dim
    constexpr int LDA = G1 ? D_MODEL : D_HID;          // A row length (halves)
    constexpr int NB  = G1 ? D_HID   : D_MODEL;        // B row length (words)
    constexpr int LDC = G1 ? D_HID   : D_MODEL;
    constexpr int T   = KD / BK;

    const int e   = blockIdx.z;
    const int cnt = g_cnt[e];
    const int m0  = blockIdx.y * BM;
    if (m0 >= cnt) return;
    const int n0  = blockIdx.x * BN;
    const int* rows = g_rows + e * NTOK;

    const __half*   A  = G1 ? g_xh : g_hidden_h;
    const uint32_t* Bp = (G1 ? g_w1h : g_w2h) + (size_t)e * (KD / 2) * NB;

    extern __shared__ char sm[];
    int* slotSm = (int*)(sm + OFF_SLOT);
    const uint32_t smBase = (uint32_t)__cvta_generic_to_shared(sm);

    const int tid  = threadIdx.x;
    const int warp = tid >> 5;
    const int lane = tid & 31;
    const int grp  = lane >> 2;
    const int qid  = lane & 3;

    const int warp_m = warp & 1;
    const int warp_n = warp >> 1;
    const int cbase  = warp_n * 32;

    if (tid < BM) {
        int gr = m0 + tid;
        slotSm[tid] = (gr < cnt) ? rows[gr] : -1;
    }
    __syncthreads();

    // ---- A staging: thread -> (row = tid>>2, kc = (tid&3)*8 halves), 16B chunk
    const int arow = tid >> 2, akc = (tid & 3) * 8;
    const int asl  = slotSm[arow];
    const int szA  = asl >= 0 ? 16 : 0;
    const __half* ap = A + (asl >= 0 ? (size_t)(G1 ? (asl >> 1) : asl) * LDA : 0) + akc;
    const uint32_t aDst = smBase + (uint32_t)(arow * ASTRH + akc) * 2;

    // ---- B staging: 2 chunks; id -> (k2row = id>>5, c4 = (id&31)*4 words), 16B
    const int br0 = tid >> 5, bc0 = (tid & 31) * 4;
    const int br1 = (tid + 256) >> 5, bc1 = ((tid + 256) & 31) * 4;
    const uint32_t* bp0 = Bp + (size_t)br0 * NB + n0 + bc0;
    const uint32_t* bp1 = Bp + (size_t)br1 * NB + n0 + bc1;
    const uint32_t bDst0 = smBase + OFF_B + (uint32_t)(br0 * BSTRW + bc0) * 4;
    const uint32_t bDst1 = smBase + OFF_B + (uint32_t)(br1 * BSTRW + bc1) * 4;

    auto issue = [&](int tt, int s) {
        cpa16(aDst + (uint32_t)s * A_BYTES, ap + tt * BK, szA);
        const size_t bk = (size_t)tt * 16 * NB;
        cpa16(bDst0 + (uint32_t)s * B_BYTES, bp0 + bk, 16);
        cpa16(bDst1 + (uint32_t)s * B_BYTES, bp1 + bk, 16);
        asm volatile("cp.async.commit_group;" ::: "memory");
    };

    float acc[2][4][4];
    #pragma unroll
    for (int i = 0; i < 2; i++)
        #pragma unroll
        for (int j = 0; j < 4; j++)
            #pragma unroll
            for (int q = 0; q < 4; q++) acc[i][j][q] = 0.f;

    issue(0, 0);
    if (T > 1) issue(1, 1);

    for (int t = 0; t < T; t++) {
        if (t + 1 < T) asm volatile("cp.async.wait_group 1;" ::: "memory");
        else           asm volatile("cp.async.wait_group 0;" ::: "memory");
        __syncthreads();    // certifies compute of t-1 done -> slot (t+2)%3 free
        if (t + 2 < T) issue(t + 2, (t + 2) % STAGES);

        const int cs = t % STAGES;
        const uint32_t* AsbW = (const uint32_t*)(sm + cs * A_BYTES);
        const uint32_t* BsbW = (const uint32_t*)(sm + OFF_B + cs * B_BYTES);
        #pragma unroll
        for (int s = 0; s < 2; s++) {
            uint32_t a[2][4];
            #pragma unroll
            for (int i = 0; i < 2; i++) {
                int mr = warp_m * 32 + i * 16 + grp;
                int base = mr * (ASTRH / 2) + s * 8 + qid;
                a[i][0] = AsbW[base];
                a[i][1] = AsbW[base + 8 * (ASTRH / 2)];
                a[i][2] = AsbW[base + 4];
                a[i][3] = AsbW[base + 8 * (ASTRH / 2) + 4];
            }
            uint32_t b[4][2];
            #pragma unroll
            for (int j = 0; j < 4; j++) {
                int base = (s * 8 + qid) * BSTRW + cbase + j * 8 + grp;
                b[j][0] = BsbW[base];
                b[j][1] = BsbW[base + 4 * BSTRW];
            }
            #pragma unroll
            for (int j = 0; j < 4; j++)
                #pragma unroll
                for (int i = 0; i < 2; i++)
                    mma_f16(acc[i][j], a[i][0], a[i][1], a[i][2], a[i][3],
                            b[j][0], b[j][1]);
        }
    }

    // epilogue: bias (+ GELU), scatter rows via slot ids
    const float* bpb = bias + (size_t)e * LDC;
    float2 bv[4];
    #pragma unroll
    for (int j = 0; j < 4; j++) {
        int c = n0 + cbase + j * 8 + 2 * qid;
        bv[j] = *(const float2*)(bpb + c);
    }
    #pragma unroll
    for (int i = 0; i < 2; i++) {
        int lbase = warp_m * 32 + i * 16 + grp;
        #pragma unroll
        for (int h = 0; h < 2; h++) {
            int lr = lbase + h * 8;
            int slot = slotSm[lr];
            if (slot >= 0) {
                #pragma unroll
                for (int j = 0; j < 4; j++) {
                    int c = n0 + cbase + j * 8 + 2 * qid;
                    float v0 = acc[i][j][2 * h + 0] + bv[j].x;
                    float v1 = acc[i][j][2 * h + 1] + bv[j].y;
                    if (G1) {
                        v0 = 0.5f * v0 * (1.f + erff(v0 * 0.70710678118654752f));
                        v1 = 0.5f * v1 * (1.f + erff(v1 * 0.70710678118654752f));
                        __half2 hv = __floats2half2_rn(v0, v1);
                        *(uint32_t*)&g_hidden_h[(size_t)slot * D_HID + c] =
                            *(uint32_t*)&hv;
                    } else {
                        *(float2*)&g_y[(size_t)slot * D_MODEL + c] =
                            make_float2(v0, v1);
                    }
                }
            }
        }
    }
}

// ---------------- weighted combine ----------------------------------------------
__global__ void combine_kernel(float* __restrict__ out) {
    int idx = blockIdx.x * blockDim.x + threadIdx.x;
    int n  = idx / (D_MODEL / 4);
    int d4 = (idx % (D_MODEL / 4)) * 4;
    float w0 = g_wt[2 * n], w1 = g_wt[2 * n + 1];
    float4 y0 = *(const float4*)&g_y[(size_t)(2 * n + 0) * D_MODEL + d4];
    float4 y1 = *(const float4*)&g_y[(size_t)(2 * n + 1) * D_MODEL + d4];
    float4 o;
    o.x = w0 * y0.x + w1 * y1.x;
    o.y = w0 * y0.y + w1 * y1.y;
    o.z = w0 * y0.z + w1 * y1.z;
    o.w = w0 * y0.w + w1 * y1.w;
    *(float4*)&out[(size_t)n * D_MODEL + d4] = o;
}

// ---------------- launcher -------------------------------------------------------
extern "C" void kernel_launch(void* const* d_in, const int* in_sizes, int n_in,
                              void* d_out, int out_size) {
    const float* x      = (const float*)d_in[0];
    const float* gate_w = (const float*)d_in[1];
    const float* w1     = (const float*)d_in[2];
    const float* b1     = (const float*)d_in[3];
    const float* w2     = (const float*)d_in[4];
    const float* b2     = (const float*)d_in[5];
    float* out = (float*)d_out;

    const int nw1 = NUM_EXPERTS * (D_MODEL / 2) * D_HID;   // packed pairs
    const int nw2 = NUM_EXPERTS * (D_HID / 2) * D_MODEL;
    const int nx4 = NTOK * D_MODEL / 4;

    reset_kernel<<<1, 32>>>();
    router_kernel<<<NTOK, 256>>>(x, gate_w);
    pre_w_kernel<<<(nw1 + 255) / 256, 256>>>(w1, 0, D_MODEL, D_HID, nw1);
    pre_w_kernel<<<(nw2 + 255) / 256, 256>>>(w2, 1, D_HID, D_MODEL, nw2);
    pre_x_kernel<<<nx4 / 256, 256>>>(x);
    moe_gemm<true><<<dim3(D_HID / BN, NTOK / BM, NUM_EXPERTS), 256, SMEM_TOTAL>>>(b1);
    moe_gemm<false><<<dim3(D_MODEL / BN, NTOK / BM, NUM_EXPERTS), 256, SMEM_TOTAL>>>(b2);
    combine_kernel<<<(NTOK * (D_MODEL / 4)) / 256, 256>>>(out);
}

// round 16
// speedup vs baseline: 2.2237x; 1.2566x over previous
#include <cuda_runtime.h>
#include <cuda_fp16.h>
#include <math.h>
#include <stdint.h>

#define D_MODEL 768
#define D_HID   3072
#define NUM_EXPERTS 8
#define NTOK    2048
#define NSLOT   (NTOK * 2)

// ---------------- device scratch (no runtime allocation allowed) ----------------
// g_xh / g_hidden_h: fp16, k-words permuted per 8-word group (w<4?2w:2(w-4)+1)
// g_w*h: fp16 k-pairs, [expert][k32-tile][pr(8)][n][2] word layout
__device__ __half   g_hidden_h[NSLOT * D_HID];
__device__ float    g_y[NSLOT * D_MODEL];
__device__ int      g_cnt[NUM_EXPERTS];
__device__ int      g_rows[NUM_EXPERTS * NTOK];
__device__ float    g_wt[NSLOT];
__device__ __half   g_xh[NTOK * D_MODEL];
__device__ uint32_t g_w1h[NUM_EXPERTS * (D_MODEL / 2) * D_HID];
__device__ uint32_t g_w2h[NUM_EXPERTS * (D_HID / 2) * D_MODEL];

// ---------------- helpers --------------------------------------------------------
__device__ __forceinline__ void mma_f16(float* c,
                                        uint32_t a0, uint32_t a1, uint32_t a2, uint32_t a3,
                                        uint32_t b0, uint32_t b1) {
    asm volatile(
        "mma.sync.aligned.m16n8k16.row.col.f32.f16.f16.f32 "
        "{%0,%1,%2,%3}, {%4,%5,%6,%7}, {%8,%9}, {%0,%1,%2,%3};"
        : "+f"(c[0]), "+f"(c[1]), "+f"(c[2]), "+f"(c[3])
        : "r"(a0), "r"(a1), "r"(a2), "r"(a3), "r"(b0), "r"(b1));
}
__device__ __forceinline__ void cpa16(uint32_t dst, const void* src, int sz) {
    asm volatile("cp.async.ca.shared.global [%0], [%1], 16, %2;"
                 :: "r"(dst), "l"(src), "r"(sz) : "memory");
}
__device__ __forceinline__ uint32_t pkh(float a, float b) {
    __half2 h = __floats2half2_rn(a, b);
    return *(uint32_t*)&h;
}

// ---------------- reset ----------------------------------------------------------
__global__ void reset_kernel() {
    if (threadIdx.x < NUM_EXPERTS) g_cnt[threadIdx.x] = 0;
}

// ---------------- fused preprocessing --------------------------------------------
// W -> pair-interleaved fp16 pack: dst word ((e*TILES+tt)*8+pr)*(N*2) + n*2 + z
//   z=0: pack(W[2*k2a][n], W[2*k2a+1][n]); z=1: same for k2b=k2a+4,
//   k2a = tt*16 + (pr>>2)*8 + (pr&3). Each thread: 2 cols -> one uint4.
template<int K, int N>
__device__ __forceinline__ void pre_w_dev(const float* __restrict__ in,
                                          uint32_t* __restrict__ out, int i) {
    constexpr int N2 = N / 2;
    int n2 = i % N2;
    int rest = i / N2;
    int pr = rest & 7;
    int rt = rest >> 3;              // e*TILES + tt, used directly
    int k2a = (rt % (K / 32)) * 16 + (pr >> 2) * 8 + (pr & 3);
    int e   = rt / (K / 32);
    const float* base = in + (size_t)e * K * N + 2 * n2;
    float2 a0 = *(const float2*)(base + (size_t)(2 * k2a + 0) * N);
    float2 a1 = *(const float2*)(base + (size_t)(2 * k2a + 1) * N);
    float2 b0 = *(const float2*)(base + (size_t)(2 * k2a + 8) * N);
    float2 b1 = *(const float2*)(base + (size_t)(2 * k2a + 9) * N);
    ((uint4*)out)[i] = make_uint4(pkh(a0.x, a1.x), pkh(b0.x, b1.x),
                                  pkh(a0.y, a1.y), pkh(b0.y, b1.y));
}
// x -> fp16 with per-group word permutation: word q -> pos 2q, q+4 -> 2q+1
__device__ __forceinline__ void pre_x_dev(const float* __restrict__ in, int i) {
    int g = i >> 2, q = i & 3;
    const float2* f2 = (const float2*)in;      // one float2 == one fp16 word
    float2 lo = f2[8 * g + q];
    float2 hi = f2[8 * g + q + 4];
    ((uint2*)g_xh)[4 * g + q] = make_uint2(pkh(lo.x, lo.y), pkh(hi.x, hi.y));
}

static constexpr int NW_BLK = 9216;            // 2359296 / 256 per weight
static constexpr int NX_BLK = 1536;            // 393216 / 256
__global__ void pre_all_kernel(const float* __restrict__ x,
                               const float* __restrict__ w1,
                               const float* __restrict__ w2) {
    int b = blockIdx.x;
    if (b < NW_BLK) {
        pre_w_dev<D_MODEL, D_HID>(w1, g_w1h, b * 256 + threadIdx.x);
    } else if (b < 2 * NW_BLK) {
        pre_w_dev<D_HID, D_MODEL>(w2, g_w2h, (b - NW_BLK) * 256 + threadIdx.x);
    } else {
        pre_x_dev(x, (b - 2 * NW_BLK) * 256 + threadIdx.x);
    }
}

// ---------------- router (exact fp32; assignment must match reference) -----------
__global__ void router_kernel(const float* __restrict__ x,
                              const float* __restrict__ gw) {
    __shared__ float xs[D_MODEL];
    __shared__ float logits[NUM_EXPERTS];
    const int n = blockIdx.x;
    const float* xr = x + (size_t)n * D_MODEL;
    for (int i = threadIdx.x; i < D_MODEL; i += blockDim.x) xs[i] = xr[i];
    __syncthreads();

    const int w = threadIdx.x >> 5, lane = threadIdx.x & 31;
    if (w < NUM_EXPERTS) {
        float s = 0.f;
        for (int d = lane; d < D_MODEL; d += 32)
            s += xs[d] * gw[d * NUM_EXPERTS + w];
        #pragma unroll
        for (int o = 16; o; o >>= 1) s += __shfl_xor_sync(0xffffffffu, s, o);
        if (lane == 0) logits[w] = s;
    }
    __syncthreads();

    if (threadIdx.x == 0) {
        int i0 = 0; float l0 = logits[0];
        #pragma unroll
        for (int e = 1; e < NUM_EXPERTS; e++)
            if (logits[e] > l0) { l0 = logits[e]; i0 = e; }
        int i1 = -1; float l1 = -INFINITY;
        #pragma unroll
        for (int e = 0; e < NUM_EXPERTS; e++)
            if (e != i0 && logits[e] > l1) { l1 = logits[e]; i1 = e; }
        float e1 = expf(l1 - l0);
        float inv = 1.f / (1.f + e1);

        int p0 = atomicAdd(&g_cnt[i0], 1);
        g_rows[i0 * NTOK + p0] = n * 2 + 0;
        g_wt[n * 2 + 0] = inv;
        int p1 = atomicAdd(&g_cnt[i1], 1);
        g_rows[i1 * NTOK + p1] = n * 2 + 1;
        g_wt[n * 2 + 1] = e1 * inv;
    }
}

// ---------------- grouped fp16 tensor-core GEMM: BM=64, BN=128, BK=32 ------------
// 8 warps 2(m)x4(n), warp tile 32x32. All operand pairs are LDS.64:
//   A smem: 64 rows x 8 f2, stride 12 f2 (96B). bank-pair (12*grp+qid) mod 16 bij.
//   B smem: 8 pr-rows x 128 f2, stride 132 f2 (1056B). (4*qid+grp+8j) mod 16 bij.
// 3-stage cp.async ring, one __syncthreads per tile.
static constexpr int BM = 64, BN = 128, BK = 32;
static constexpr int A_ROWB  = 96;                     // bytes per A smem row
static constexpr int A_BYTES = BM * A_ROWB;            // 6144
static constexpr int B_ROWB  = 264 * 4;                // 1056 B per pr-row
static constexpr int B_BYTES = 8 * B_ROWB;             // 8448
static constexpr int STAGES = 3;
static constexpr int OFF_B    = STAGES * A_BYTES;      // 18432
static constexpr int OFF_SLOT = OFF_B + STAGES * B_BYTES;  // 43776
static constexpr int SMEM_TOTAL = OFF_SLOT + BM * 4;       // 44032

template<bool G1>
__global__ void __launch_bounds__(256, 2)
moe_gemm(const float* __restrict__ bias) {
    constexpr int KD  = G1 ? D_MODEL : D_HID;
    constexpr int LDA = G1 ? D_MODEL : D_HID;          // A row halves
    constexpr int NB  = G1 ? D_HID   : D_MODEL;        // output cols
    constexpr int NB2 = NB * 2;                        // B words per pr-row
    constexpr int LDC = G1 ? D_HID   : D_MODEL;
    constexpr int T   = KD / BK;

    const int e   = blockIdx.z;
    const int cnt = g_cnt[e];
    const int m0  = blockIdx.y * BM;
    if (m0 >= cnt) return;
    const int n0  = blockIdx.x * BN;
    const int* rows = g_rows + e * NTOK;

    const __half*   A  = G1 ? g_xh : g_hidden_h;
    const uint32_t* Bp = (G1 ? g_w1h : g_w2h) + (size_t)e * (KD / 2) * NB;

    extern __shared__ char sm[];
    int* slotSm = (int*)(sm + OFF_SLOT);
    const uint32_t smBase = (uint32_t)__cvta_generic_to_shared(sm);

    const int tid  = threadIdx.x;
    const int warp = tid >> 5;
    const int lane = tid & 31;
    const int grp  = lane >> 2;
    const int qid  = lane & 3;

    const int warp_m = warp & 1;
    const int warp_n = warp >> 1;
    const int cbase  = warp_n * 32;

    if (tid < BM) {
        int gr = m0 + tid;
        slotSm[tid] = (gr < cnt) ? rows[gr] : -1;
    }
    __syncthreads();

    // ---- A staging: thread -> (row = tid>>2, chunk c = tid&3 of 8 halves)
    const int arow = tid >> 2, ac = tid & 3;
    const int asl  = slotSm[arow];
    const int szA  = asl >= 0 ? 16 : 0;
    const __half* ap = A + (asl >= 0 ? (size_t)(G1 ? (asl >> 1) : asl) * LDA : 0) + ac * 8;
    const uint32_t aDst = smBase + (uint32_t)(arow * A_ROWB + ac * 16);

    // ---- B staging: 2 chunks/thread; id -> (pr = id>>6, cw = (id&63)*4 words)
    const int pr0 = tid >> 6,         cw0 = (tid & 63) * 4;
    const int pr1 = (tid + 256) >> 6, cw1 = cw0;
    const uint32_t* bp0 = Bp + (size_t)pr0 * NB2 + n0 * 2 + cw0;
    const uint32_t* bp1 = Bp + (size_t)pr1 * NB2 + n0 * 2 + cw1;
    const uint32_t bDst0 = smBase + OFF_B + (uint32_t)(pr0 * B_ROWB + cw0 * 4);
    const uint32_t bDst1 = smBase + OFF_B + (uint32_t)(pr1 * B_ROWB + cw1 * 4);

    auto issue = [&](int tt, int s) {
        cpa16(aDst + (uint32_t)s * A_BYTES, ap + tt * BK, szA);
        const size_t bk = (size_t)tt * 8 * NB2;
        cpa16(bDst0 + (uint32_t)s * B_BYTES, bp0 + bk, 16);
        cpa16(bDst1 + (uint32_t)s * B_BYTES, bp1 + bk, 16);
        asm volatile("cp.async.commit_group;" ::: "memory");
    };

    float acc[2][4][4];
    #pragma unroll
    for (int i = 0; i < 2; i++)
        #pragma unroll
        for (int j = 0; j < 4; j++)
            #pragma unroll
            for (int q = 0; q < 4; q++) acc[i][j][q] = 0.f;

    issue(0, 0);
    if (T > 1) issue(1, 1);

    for (int t = 0; t < T; t++) {
        if (t + 1 < T) asm volatile("cp.async.wait_group 1;" ::: "memory");
        else           asm volatile("cp.async.wait_group 0;" ::: "memory");
        __syncthreads();
        if (t + 2 < T) issue(t + 2, (t + 2) % STAGES);

        const int cs = t % STAGES;
        const uint2* AsbF2 = (const uint2*)(sm + cs * A_BYTES);
        const uint2* BsbF2 = (const uint2*)(sm + OFF_B + cs * B_BYTES);
        #pragma unroll
        for (int s = 0; s < 2; s++) {
            uint2 a02[2], a13[2];
            #pragma unroll
            for (int i = 0; i < 2; i++) {
                int mr = warp_m * 32 + i * 16 + grp;
                a02[i] = AsbF2[mr * 12 + s * 4 + qid];
                a13[i] = AsbF2[(mr + 8) * 12 + s * 4 + qid];
            }
            uint2 b01[4];
            #pragma unroll
            for (int j = 0; j < 4; j++)
                b01[j] = BsbF2[(s * 4 + qid) * 132 + cbase + j * 8 + grp];
            #pragma unroll
            for (int j = 0; j < 4; j++)
                #pragma unroll
                for (int i = 0; i < 2; i++)
                    mma_f16(acc[i][j], a02[i].x, a13[i].x, a02[i].y, a13[i].y,
                            b01[j].x, b01[j].y);
        }
    }

    // epilogue: bias (+ GELU), scatter via slot ids (hidden stored k-permuted)
    const float* bpb = bias + (size_t)e * LDC;
    float2 bv[4];
    #pragma unroll
    for (int j = 0; j < 4; j++) {
        int c = n0 + cbase + j * 8 + 2 * qid;
        bv[j] = *(const float2*)(bpb + c);
    }
    #pragma unroll
    for (int i = 0; i < 2; i++) {
        int lbase = warp_m * 32 + i * 16 + grp;
        #pragma unroll
        for (int h = 0; h < 2; h++) {
            int lr = lbase + h * 8;
            int slot = slotSm[lr];
            if (slot >= 0) {
                #pragma unroll
                for (int j = 0; j < 4; j++) {
                    int c = n0 + cbase + j * 8 + 2 * qid;
                    float v0 = acc[i][j][2 * h + 0] + bv[j].x;
                    float v1 = acc[i][j][2 * h + 1] + bv[j].y;
                    if (G1) {
                        v0 = 0.5f * v0 * (1.f + erff(v0 * 0.70710678118654752f));
                        v1 = 0.5f * v1 * (1.f + erff(v1 * 0.70710678118654752f));
                        int w = c >> 1, l = w & 7;
                        int wp = (w & ~7) | (l < 4 ? (l << 1) : (((l - 4) << 1) | 1));
                        __half2 hv = __floats2half2_rn(v0, v1);
                        *(uint32_t*)&g_hidden_h[(size_t)slot * D_HID + 2 * wp] =
                            *(uint32_t*)&hv;
                    } else {
                        *(float2*)&g_y[(size_t)slot * D_MODEL + c] =
                            make_float2(v0, v1);
                    }
                }
            }
        }
    }
}

// ---------------- weighted combine ----------------------------------------------
__global__ void combine_kernel(float* __restrict__ out) {
    int idx = blockIdx.x * blockDim.x + threadIdx.x;
    int n  = idx / (D_MODEL / 4);
    int d4 = (idx % (D_MODEL / 4)) * 4;
    float w0 = g_wt[2 * n], w1 = g_wt[2 * n + 1];
    float4 y0 = *(const float4*)&g_y[(size_t)(2 * n + 0) * D_MODEL + d4];
    float4 y1 = *(const float4*)&g_y[(size_t)(2 * n + 1) * D_MODEL + d4];
    float4 o;
    o.x = w0 * y0.x + w1 * y1.x;
    o.y = w0 * y0.y + w1 * y1.y;
    o.z = w0 * y0.z + w1 * y1.z;
    o.w = w0 * y0.w + w1 * y1.w;
    *(float4*)&out[(size_t)n * D_MODEL + d4] = o;
}

// ---------------- launcher -------------------------------------------------------
extern "C" void kernel_launch(void* const* d_in, const int* in_sizes, int n_in,
                              void* d_out, int out_size) {
    const float* x      = (const float*)d_in[0];
    const float* gate_w = (const float*)d_in[1];
    const float* w1     = (const float*)d_in[2];
    const float* b1     = (const float*)d_in[3];
    const float* w2     = (const float*)d_in[4];
    const float* b2     = (const float*)d_in[5];
    float* out = (float*)d_out;

    reset_kernel<<<1, 32>>>();
    router_kernel<<<NTOK, 256>>>(x, gate_w);
    pre_all_kernel<<<2 * NW_BLK + NX_BLK, 256>>>(x, w1, w2);
    moe_gemm<true><<<dim3(D_HID / BN, NTOK / BM, NUM_EXPERTS), 256, SMEM_TOTAL>>>(b1);
    moe_gemm<false><<<dim3(D_MODEL / BN, NTOK / BM, NUM_EXPERTS), 256, SMEM_TOTAL>>>(b2);
    combine_kernel<<<(NTOK * (D_MODEL / 4)) / 256, 256>>>(out);
}